// round 12
// baseline (speedup 1.0000x reference)
#include <cuda_runtime.h>
#include <cuda_bf16.h>
#include <cuda_fp16.h>
#include <math.h>
#include <stdint.h>

// ---------------- geometry ----------------
#define NB     2
#define NC     8
#define NV     360
#define ND     512
#define RR     11
#define HID    176
#define OC     88
#define NP     (NV*ND)
#define LL     (NP*RR)
#define NIDX   (128*128*360)

#define MT     128          // d positions per block
#define KPIT   184          // fp16 col pitch (368B rows -> conflict-free ldmatrix)
#define XP     136          // x_s pitch (floats)
#define NTHR   384          // 12 warps

// SMEM byte offsets (conv)
#define SM_X     0          // 8*136*4      = 4352
#define SM_W1    4352       // 176*25*4     = 17600
#define SM_B1    21952      // 176*4        = 704
#define SM_B2    22656      // 88*4 pad     = 384
#define SM_HB    23040      // 132*184*2    = 48576   (H fp16)
#define SM_BS    71616      // 96*184*2     = 35328   (one B tap)
#define SM_TOT   106944

#define BIMG    (96 * KPIT)             // 17664 halves per tap
#define BCHUNK  (BIMG * 2)              // 35328 bytes

// scratch (no cudaMalloc allowed)
__device__ __half g_Ah[2u * (unsigned)LL * 8u];          // fp16 table ~65MB
__device__ __align__(16) __half g_Bimg[3 * BIMG];        // [t][96*184]
__device__ int g_sink;

// ---------------- helpers ----------------
__device__ __forceinline__ uint32_t smem_u32(const void* p) {
    uint32_t a;
    asm("{ .reg .u64 t; cvta.to.shared.u64 t, %1; cvt.u32.u64 %0, t; }"
        : "=r"(a) : "l"(p));
    return a;
}

#define LDM4(d, addr)                                                        \
    asm volatile("ldmatrix.sync.aligned.m8n8.x4.shared.b16 "                 \
                 "{%0,%1,%2,%3}, [%4];"                                      \
                 : "=r"((d)[0]), "=r"((d)[1]), "=r"((d)[2]), "=r"((d)[3])    \
                 : "r"(addr) : "memory")

#define MMA(c, a, b0, b1)                                                    \
    asm volatile("mma.sync.aligned.m16n8k16.row.col.f32.f16.f16.f32 "        \
                 "{%0,%1,%2,%3},{%4,%5,%6,%7},{%8,%9},{%0,%1,%2,%3};"        \
                 : "+f"((c)[0]), "+f"((c)[1]), "+f"((c)[2]), "+f"((c)[3])    \
                 : "r"((a)[0]), "r"((a)[1]), "r"((a)[2]), "r"((a)[3]),       \
                   "r"(b0), "r"(b1))

#define CP16(dst, src)                                                       \
    asm volatile("cp.async.cg.shared.global [%0], [%1], 16;"                 \
                 :: "r"(dst), "l"(src) : "memory")
#define CPCOMMIT() asm volatile("cp.async.commit_group;" ::: "memory")
#define CPWAIT0()  asm volatile("cp.async.wait_group 0;"  ::: "memory")

// exact-accuracy cheap gelu: erf via A&S 7.1.26 (|eps| <= 1.5e-7)
__device__ __forceinline__ float gelu_f(float x) {
    float z = x * 0.70710678118654752f;
    float a = fabsf(z);
    float t = __fdividef(1.0f, fmaf(0.3275911f, a, 1.0f));
    float p = t * fmaf(t, fmaf(t, fmaf(t, fmaf(t, 1.061405429f, -1.453152027f),
                                       1.421413741f), -0.284496736f),
                       0.254829592f);
    float e = __expf(-a * a);
    float erfa = fmaf(-p, e, 1.0f);
    float erfz = copysignf(erfa, z);
    return 0.5f * x * (1.0f + erfz);
}

// ---- dummies: shift ncu -s alignment so capture lands on conv_tc ----
__global__ void knop() { g_sink = 1; }

// ---- prep: fc2_w [88][176][3] -> per-tap contiguous fp16 images ----
__global__ void prep_B(const float* __restrict__ w2) {
    int i = blockIdx.x * 256 + threadIdx.x;     // over 3*96*184
    if (i >= 3 * BIMG) return;
    int k = i % KPIT;
    int n = (i / KPIT) % 96;
    int t = i / BIMG;
    float v = 0.f;
    if (n < OC && k < HID) v = w2[((size_t)n * HID + k) * 3 + t];
    g_Bimg[(size_t)t * BIMG + (size_t)n * KPIT + k] = __float2half_rn(v);
}

// ---------------- fused conv1+gelu + warp-MMA conv2 -> fp16 table ----------------
__global__ __launch_bounds__(NTHR, 2)
void conv_tc(const float* __restrict__ input,
             const float* __restrict__ w1,
             const float* __restrict__ b1,
             const float* __restrict__ b2) {
    extern __shared__ char smem[];
    const uint32_t sb = smem_u32(smem);
    float* x_s = (float*)(smem + SM_X);
    float* w1s = (float*)(smem + SM_W1);
    float* b1s = (float*)(smem + SM_B1);
    float* b2s = (float*)(smem + SM_B2);

    const int tid  = threadIdx.x;
    const int wid  = tid >> 5;
    const int lane = tid & 31;
    const int blk  = blockIdx.x;
    const int tile = blk & 3;
    const int bv   = blk >> 2;
    const int b    = bv / NV;
    const int v    = bv - b * NV;
    const int d0   = tile * MT;

    // ---- stage x halo, conv1 weights, biases ----
    for (int i = tid; i < 8 * XP; i += NTHR) {
        int ci = i / XP, j = i - ci * XP;
        int dG = d0 - 2 + j;
        float val = 0.f;
        if ((unsigned)dG < (unsigned)ND)
            val = input[(((size_t)(b * NC + ci) * NV + v) * ND) + dG];
        x_s[i] = val;
    }
    for (int i = tid; i < HID * 24; i += NTHR)
        w1s[(i / 24) * 25 + (i % 24)] = w1[i];
    for (int i = tid; i < HID; i += NTHR) b1s[i] = b1[i];
    for (int i = tid; i < OC; i += NTHR)  b2s[i] = b2[i];

    // ---- async prefetch B tap 0 (overlaps conv1) ----
    {
        const char* src = (const char*)g_Bimg;
        for (int i = tid; i < BCHUNK / 16; i += NTHR)
            CP16(sb + SM_BS + i * 16, src + i * 16);
        CPCOMMIT();
    }
    __syncthreads();

    // ---- conv1 + gelu -> H[dd][hc] fp16 ----
    for (int u = tid; u < 33 * HID; u += NTHR) {
        int hc  = u % HID;                // lanes -> consecutive hc
        int ch  = u / HID;
        int ddb = ch * 4;

        float a4[4] = {b1s[hc], b1s[hc], b1s[hc], b1s[hc]};
        const float* wr = w1s + hc * 25;
#pragma unroll
        for (int ci = 0; ci < 8; ++ci) {
            const float* xr = x_s + ci * XP + ddb;
            float4 xa = *(const float4*)xr;
            float2 xb = *(const float2*)(xr + 4);
            float w0 = wr[ci * 3 + 0], w1v = wr[ci * 3 + 1], w2v = wr[ci * 3 + 2];
            float xv[6] = {xa.x, xa.y, xa.z, xa.w, xb.x, xb.y};
#pragma unroll
            for (int q = 0; q < 4; ++q) {
                a4[q] = fmaf(xv[q + 0], w0, a4[q]);
                a4[q] = fmaf(xv[q + 1], w1v, a4[q]);
                a4[q] = fmaf(xv[q + 2], w2v, a4[q]);
            }
        }
#pragma unroll
        for (int q = 0; q < 4; ++q) {
            int dd = ddb + q;                 // dd in [0,132)
            int dG = d0 - 1 + dd;
            float s = 0.f;
            if ((unsigned)dG < (unsigned)ND) s = gelu_f(a4[q]);
            ((__half*)(smem + SM_HB))[(size_t)dd * KPIT + hc] = __float2half_rn(s);
        }
    }
    CPWAIT0();
    __syncthreads();   // H + B(0) ready

    // ---- warp MMA: 4x3 warp grid, warp tile 32m x 32n ----
    const int m0 = (wid & 3) * 32;
    const int n0 = (wid >> 2) * 32;

    float acc[2][4][4];
#pragma unroll
    for (int i = 0; i < 2; ++i)
#pragma unroll
        for (int j = 0; j < 4; ++j)
#pragma unroll
            for (int q = 0; q < 4; ++q) acc[i][j][q] = 0.f;

    const uint32_t aRel = ((uint32_t)(m0 + (lane & 15)) * KPIT +
                           (uint32_t)(lane >> 4) * 8) * 2;
    const int g = lane >> 3;
    const uint32_t bRel = ((uint32_t)(n0 + (g >> 1) * 8 + (lane & 7)) * KPIT +
                           (uint32_t)(g & 1) * 8) * 2;
    const uint32_t ROWB = KPIT * 2;        // 368 bytes

#pragma unroll 1
    for (int t = 0; t < 3; ++t) {
        uint32_t aA = sb + SM_HB + aRel + (uint32_t)t * ROWB;
        uint32_t bB = sb + SM_BS + bRel;

#pragma unroll 1
        for (int ks = 0; ks < 11; ++ks) {
            uint32_t ah0[4], ah1[4];
            LDM4(ah0, aA);
            LDM4(ah1, aA + 16 * ROWB);
            uint32_t bb[2][4];
            LDM4(bb[0], bB);
            LDM4(bb[1], bB + 16 * ROWB);

#pragma unroll
            for (int j = 0; j < 4; ++j) {
                const int jj = j >> 1, pp = (j & 1) * 2;
                MMA(acc[0][j], ah0, bb[jj][pp], bb[jj][pp + 1]);
                MMA(acc[1][j], ah1, bb[jj][pp], bb[jj][pp + 1]);
            }
            aA += 32; bB += 32;
        }

        if (t < 2) {
            __syncthreads();   // B buffer free
            const char* src = (const char*)g_Bimg + (size_t)(t + 1) * BCHUNK;
            for (int i = tid; i < BCHUNK / 16; i += NTHR)
                CP16(sb + SM_BS + i * 16, src + i * 16);
            CPCOMMIT();
            CPWAIT0();
            __syncthreads();
        }
    }
    __syncthreads();   // all H reads done; reuse region for y staging

    // ---- epilogue: acc + bias -> fp16, permute oc -> (rr*8+ci) ----
    __half* y_s = (__half*)(smem + SM_HB);   // [128][96] halves
    const int rbase = (lane >> 2);
    const int cbase = (lane & 3) * 2;
#pragma unroll
    for (int i = 0; i < 2; ++i) {
#pragma unroll
        for (int j = 0; j < 4; ++j) {
            int col0 = n0 + j * 8 + cbase;
#pragma unroll
            for (int rh2 = 0; rh2 < 2; ++rh2) {
                int row = m0 + i * 16 + rbase + rh2 * 8;
#pragma unroll
                for (int ch2 = 0; ch2 < 2; ++ch2) {
                    int col = col0 + ch2;
                    if (col < OC) {
                        int ci = col / RR, rm = col - ci * RR;
                        y_s[(size_t)row * 96 + rm * 8 + ci] =
                            __float2half_rn(acc[i][j][rh2 * 2 + ch2] + b2s[col]);
                    }
                }
            }
        }
    }
    __syncthreads();

    // coalesced global write: g_Ah[(b*NP + v*512 + d0 + m)*88 + (r*8+c)]
    size_t gbase = ((size_t)b * NP + (size_t)v * ND + d0) * OC;
    for (int i = tid; i < MT * (OC / 2); i += NTHR) {
        int od = i / (OC / 2);
        int cu = i - od * (OC / 2);
        ((uint32_t*)(g_Ah + gbase + (size_t)od * OC))[cu] =
            ((const uint32_t*)(y_s + (size_t)od * 96))[cu];
    }
}

// ---------------- gather: warp-cooperative staged loads ----------------
__device__ __forceinline__ void stg_cs(float* p, float v) {
    asm volatile("st.global.cs.f32 [%0], %1;" :: "l"(p), "f"(v));
}

#define GPITCH 144   // stage row pitch bytes (16B-mult; 36 words, phase-conflict-free)

__global__ __launch_bounds__(256)
void gather_kernel(const float* __restrict__ idxs, float* __restrict__ out) {
    __shared__ int s_li[256];
    __shared__ int s_hi[256];
    __shared__ __align__(16) char stage[256 * GPITCH];   // 36864B

    const int jloc = threadIdx.x;
    const int j = blockIdx.x * 256 + jloc;

    float t  = idxs[j];
    float il = floorf(t);
    float w  = t - il;
    float w5 = w * 5.0f;
    float fw = floorf(w5);
    float lw = w5 - fw;

    int li = (int)(il * 11.0f + 5.0f + fw);
    int hi = li + 6;
    if (hi >= LL - 1) hi = LL - 2;

    s_li[jloc] = li;
    s_hi[jloc] = hi;
    __syncthreads();

    // cooperative load: 8 lanes serve one j's 8 rows (b0/b1 x li,li+1,hi,hi+1)
    const int rsel = jloc & 7;       // row slot within a j
    const int jt   = jloc >> 3;      // base j-local served
    const int bb   = rsel >> 2;      // batch
    const int rr   = rsel & 3;       // 0,1 -> li+rr ; 2,3 -> hi+rr-2
    const size_t boff = (size_t)bb * (size_t)LL * 8u;
#pragma unroll
    for (int rnd = 0; rnd < 8; ++rnd) {
        int jj  = jt + rnd * 32;
        int row = (rr < 2) ? (s_li[jj] + rr) : (s_hi[jj] + (rr - 2));
        uint4 d = __ldg((const uint4*)(g_Ah + boff + (size_t)row * 8u));
        *(uint4*)(stage + jj * GPITCH + rsel * 16) = d;
    }
    __syncthreads();

    float omlw = 1.0f - lw;
    float omw  = 1.0f - w;
    const char* my = stage + jloc * GPITCH;

#pragma unroll
    for (int b = 0; b < 2; ++b) {
        uint4 va = *(const uint4*)(my + (b * 4 + 0) * 16);   // li
        uint4 vb = *(const uint4*)(my + (b * 4 + 1) * 16);   // li+1
        uint4 ua = *(const uint4*)(my + (b * 4 + 2) * 16);   // hi
        uint4 ub = *(const uint4*)(my + (b * 4 + 3) * 16);   // hi+1

        size_t obase = (size_t)b * 8u * (size_t)NIDX + (size_t)j;
#pragma unroll
        for (int p = 0; p < 4; ++p) {
            float2 a0 = __half22float2(((const __half2*)&va)[p]);
            float2 a1 = __half22float2(((const __half2*)&vb)[p]);
            float2 c0 = __half22float2(((const __half2*)&ua)[p]);
            float2 c1 = __half22float2(((const __half2*)&ub)[p]);

            float lowx  = a0.x * omlw + a1.x * lw;
            float lowy  = a0.y * omlw + a1.y * lw;
            float highx = c0.x * omlw + c1.x * lw;
            float highy = c0.y * omlw + c1.y * lw;

            stg_cs(out + obase + (size_t)(2 * p + 0) * NIDX, lowx * omw + highx * w);
            stg_cs(out + obase + (size_t)(2 * p + 1) * NIDX, lowy * omw + highy * w);
        }
    }
}

// ---------------- launch ----------------
extern "C" void kernel_launch(void* const* d_in, const int* in_sizes, int n_in,
                              void* d_out, int out_size) {
    const float* input = (const float*)d_in[0];
    const float* idxs  = (const float*)d_in[1];
    const float* fc1w  = (const float*)d_in[2];
    const float* fc1b  = (const float*)d_in[3];
    const float* fc2w  = (const float*)d_in[4];
    const float* fc2b  = (const float*)d_in[5];
    float* out = (float*)d_out;

    cudaFuncSetAttribute(conv_tc, cudaFuncAttributeMaxDynamicSharedMemorySize,
                         SM_TOT);

    knop<<<1, 1>>>();   // alignment: sample index 5 (2 hidden) -> idx 3 = conv_tc
    prep_B<<<(3 * BIMG + 255) / 256, 256>>>(fc2w);
    knop<<<1, 1>>>();
    conv_tc<<<NB * NV * (ND / MT), NTHR, SM_TOT>>>(input, fc1w, fc1b, fc2b);
    gather_kernel<<<NIDX / 256, 256>>>(idxs, out);
}

// round 13
// speedup vs baseline: 1.1615x; 1.1615x over previous
#include <cuda_runtime.h>
#include <cuda_bf16.h>
#include <cuda_fp16.h>
#include <math.h>
#include <stdint.h>

// ---------------- geometry ----------------
#define NB     2
#define NC     8
#define NV     360
#define ND     512
#define RR     11
#define HID    176
#define OC     88
#define NP     (NV*ND)
#define LL     (NP*RR)
#define NIDX   (128*128*360)

#define MT     128          // d positions per block
#define KPIT   184          // fp16 col pitch (368B rows -> conflict-free ldmatrix)
#define XP     136          // x_s pitch (floats)
#define NTHR   384          // 12 warps

// SMEM byte offsets
#define SM_X     0          // 8*136*4      = 4352
#define SM_W1    4352       // 176*25*4     = 17600
#define SM_B1    21952      // 176*4        = 704
#define SM_B2    22656      // 88*4 pad     = 384
#define SM_PERM  23040      // 88*4 pad     = 384  (wait: overlaps SM_HB below? no - shift HB)
#define SM_HB    23424      // 132*184*2    = 48576   (H fp16)
#define SM_BS    72000      // 96*184*2     = 35328   (one B tap)
#define SM_TOT   107328

#define BIMG    (96 * KPIT)             // 17664 halves per tap
#define BCHUNK  (BIMG * 2)              // 35328 bytes

// scratch (no cudaMalloc allowed)
__device__ __half g_Ah[2u * (unsigned)LL * 8u];          // fp16 table ~65MB
__device__ __align__(16) __half g_Bimg[3 * BIMG];        // [t][96*184]
__device__ int g_sink;

// ---------------- helpers ----------------
__device__ __forceinline__ uint32_t smem_u32(const void* p) {
    uint32_t a;
    asm("{ .reg .u64 t; cvta.to.shared.u64 t, %1; cvt.u32.u64 %0, t; }"
        : "=r"(a) : "l"(p));
    return a;
}

#define LDM4(d, addr)                                                        \
    asm volatile("ldmatrix.sync.aligned.m8n8.x4.shared.b16 "                 \
                 "{%0,%1,%2,%3}, [%4];"                                      \
                 : "=r"((d)[0]), "=r"((d)[1]), "=r"((d)[2]), "=r"((d)[3])    \
                 : "r"(addr) : "memory")

#define MMA(c, a, b0, b1)                                                    \
    asm volatile("mma.sync.aligned.m16n8k16.row.col.f32.f16.f16.f32 "        \
                 "{%0,%1,%2,%3},{%4,%5,%6,%7},{%8,%9},{%0,%1,%2,%3};"        \
                 : "+f"((c)[0]), "+f"((c)[1]), "+f"((c)[2]), "+f"((c)[3])    \
                 : "r"((a)[0]), "r"((a)[1]), "r"((a)[2]), "r"((a)[3]),       \
                   "r"(b0), "r"(b1))

#define CP16(dst, src)                                                       \
    asm volatile("cp.async.cg.shared.global [%0], [%1], 16;"                 \
                 :: "r"(dst), "l"(src) : "memory")
#define CPCOMMIT() asm volatile("cp.async.commit_group;" ::: "memory")
#define CPWAIT0()  asm volatile("cp.async.wait_group 0;"  ::: "memory")

// tanh-form gelu (~10 instr). |err| <= ~1.5e-4 abs, below fp16 H quant.
// gelu(x) = x * (1 - 1/(1 + e^{2u})), u = 0.7978845608*(x + 0.044715 x^3)
__device__ __forceinline__ float gelu_f(float x) {
    float t  = x * x;
    float u2 = x * fmaf(0.044715f, t, 1.0f) * 1.5957691216f;  // = 2u
    float e  = __expf(u2);
    float r  = __fdividef(1.0f, e + 1.0f);
    return fmaf(-x, r, x);
}

// ---- dummy: shifts ncu -s alignment so capture lands on conv_tc ----
__global__ void knop() { g_sink = 1; }

// ---- prep: fc2_w [88][176][3] -> per-tap contiguous fp16 images ----
__global__ void prep_B(const float* __restrict__ w2) {
    int i = blockIdx.x * 256 + threadIdx.x;     // over 3*96*184
    if (i >= 3 * BIMG) return;
    int k = i % KPIT;
    int n = (i / KPIT) % 96;
    int t = i / BIMG;
    float v = 0.f;
    if (n < OC && k < HID) v = w2[((size_t)n * HID + k) * 3 + t];
    g_Bimg[(size_t)t * BIMG + (size_t)n * KPIT + k] = __float2half_rn(v);
}

// ---------------- fused conv1+gelu + warp-MMA conv2 -> fp16 table ----------------
__global__ __launch_bounds__(NTHR, 2)
void conv_tc(const float* __restrict__ input,
             const float* __restrict__ w1,
             const float* __restrict__ b1,
             const float* __restrict__ b2) {
    extern __shared__ char smem[];
    const uint32_t sb = smem_u32(smem);
    float* x_s  = (float*)(smem + SM_X);
    float* w1s  = (float*)(smem + SM_W1);
    float* b1s  = (float*)(smem + SM_B1);
    float* b2s  = (float*)(smem + SM_B2);
    int*   perm = (int*)(smem + SM_PERM);

    const int tid  = threadIdx.x;
    const int wid  = tid >> 5;
    const int lane = tid & 31;
    const int blk  = blockIdx.x;
    const int tile = blk & 3;
    const int bv   = blk >> 2;
    const int b    = bv / NV;
    const int v    = bv - b * NV;
    const int d0   = tile * MT;

    // ---- stage x halo, conv1 weights, biases, perm LUT ----
    for (int i = tid; i < 8 * XP; i += NTHR) {
        int ci = i / XP, j = i - ci * XP;
        int dG = d0 - 2 + j;
        float val = 0.f;
        if ((unsigned)dG < (unsigned)ND)
            val = input[(((size_t)(b * NC + ci) * NV + v) * ND) + dG];
        x_s[i] = val;
    }
    for (int i = tid; i < HID * 24; i += NTHR)
        w1s[(i / 24) * 25 + (i % 24)] = w1[i];
    for (int i = tid; i < HID; i += NTHR) b1s[i] = b1[i];
    if (tid < OC) {
        b2s[tid] = b2[tid];
        perm[tid] = (tid % RR) * 8 + tid / RR;
    }

    // ---- async prefetch B tap 0 (overlaps conv1) ----
    {
        const char* src = (const char*)g_Bimg;
        for (int i = tid; i < BCHUNK / 16; i += NTHR)
            CP16(sb + SM_BS + i * 16, src + i * 16);
        CPCOMMIT();
    }
    __syncthreads();

    // ---- conv1 + gelu -> H[dd][hc] fp16 ; 8 d per unit ----
    for (int u = tid; u < 17 * HID; u += NTHR) {
        int hc  = u % HID;                // lanes -> consecutive hc
        int ch  = u / HID;                // 0..16
        int ddb = ch * 8;                 // 0..128

        float bia = b1s[hc];
        float a8[8] = {bia, bia, bia, bia, bia, bia, bia, bia};
        const float* wr = w1s + hc * 25;
#pragma unroll
        for (int ci = 0; ci < 8; ++ci) {
            const float* xr = x_s + ci * XP + ddb;
            // reads ddb..ddb+9; for ch==16 the tail (q>=4) is discarded,
            // and the 2-float overread stays inside the smem allocation.
            float4 xa = *(const float4*)xr;
            float4 xb = *(const float4*)(xr + 4);
            float2 xc = *(const float2*)(xr + 8);
            float w0 = wr[ci * 3 + 0], w1v = wr[ci * 3 + 1], w2v = wr[ci * 3 + 2];
            float xv[10] = {xa.x, xa.y, xa.z, xa.w, xb.x, xb.y, xb.z, xb.w,
                            xc.x, xc.y};
#pragma unroll
            for (int q = 0; q < 8; ++q) {
                a8[q] = fmaf(xv[q + 0], w0, a8[q]);
                a8[q] = fmaf(xv[q + 1], w1v, a8[q]);
                a8[q] = fmaf(xv[q + 2], w2v, a8[q]);
            }
        }
#pragma unroll
        for (int q = 0; q < 8; ++q) {
            int dd = ddb + q;                 // dd in [0,136), valid < 132
            if (dd < 132) {
                int dG = d0 - 1 + dd;
                float s = 0.f;
                if ((unsigned)dG < (unsigned)ND) s = gelu_f(a8[q]);
                ((__half*)(smem + SM_HB))[(size_t)dd * KPIT + hc] =
                    __float2half_rn(s);
            }
        }
    }
    CPWAIT0();
    __syncthreads();   // H + B(0) ready

    // ---- warp MMA: 4x3 warp grid, warp tile 32m x 32n ----
    const int m0 = (wid & 3) * 32;
    const int n0 = (wid >> 2) * 32;

    float acc[2][4][4];
#pragma unroll
    for (int i = 0; i < 2; ++i)
#pragma unroll
        for (int j = 0; j < 4; ++j)
#pragma unroll
            for (int q = 0; q < 4; ++q) acc[i][j][q] = 0.f;

    const uint32_t aRel = ((uint32_t)(m0 + (lane & 15)) * KPIT +
                           (uint32_t)(lane >> 4) * 8) * 2;
    const int g = lane >> 3;
    const uint32_t bRel = ((uint32_t)(n0 + (g >> 1) * 8 + (lane & 7)) * KPIT +
                           (uint32_t)(g & 1) * 8) * 2;
    const uint32_t ROWB = KPIT * 2;        // 368 bytes

#pragma unroll 1
    for (int t = 0; t < 3; ++t) {
        uint32_t aA = sb + SM_HB + aRel + (uint32_t)t * ROWB;
        uint32_t bB = sb + SM_BS + bRel;

#pragma unroll 1
        for (int ks = 0; ks < 11; ++ks) {
            uint32_t ah0[4], ah1[4];
            LDM4(ah0, aA);
            LDM4(ah1, aA + 16 * ROWB);
            uint32_t bb[2][4];
            LDM4(bb[0], bB);
            LDM4(bb[1], bB + 16 * ROWB);

#pragma unroll
            for (int j = 0; j < 4; ++j) {
                const int jj = j >> 1, pp = (j & 1) * 2;
                MMA(acc[0][j], ah0, bb[jj][pp], bb[jj][pp + 1]);
                MMA(acc[1][j], ah1, bb[jj][pp], bb[jj][pp + 1]);
            }
            aA += 32; bB += 32;
        }

        if (t < 2) {
            __syncthreads();   // B buffer free
            const char* src = (const char*)g_Bimg + (size_t)(t + 1) * BCHUNK;
            for (int i = tid; i < BCHUNK / 16; i += NTHR)
                CP16(sb + SM_BS + i * 16, src + i * 16);
            CPCOMMIT();
            CPWAIT0();
            __syncthreads();
        }
    }

    // ---- epilogue: acc + bias -> fp16, permuted via LUT ----
    const int rbase = (lane >> 2);
    const int cbase = (lane & 3) * 2;
    int pcol[4][2];
    float pbias[4][2];
#pragma unroll
    for (int j = 0; j < 4; ++j)
#pragma unroll
        for (int ch2 = 0; ch2 < 2; ++ch2) {
            int col = n0 + j * 8 + cbase + ch2;
            if (col < OC) { pcol[j][ch2] = perm[col]; pbias[j][ch2] = b2s[col]; }
            else pcol[j][ch2] = -1;
        }
    __syncthreads();   // all H/perm reads done; reuse region for y staging

    __half* y_s = (__half*)(smem + SM_HB);   // [128][96] halves
#pragma unroll
    for (int i = 0; i < 2; ++i) {
#pragma unroll
        for (int j = 0; j < 4; ++j) {
#pragma unroll
            for (int rh2 = 0; rh2 < 2; ++rh2) {
                int row = m0 + i * 16 + rbase + rh2 * 8;
#pragma unroll
                for (int ch2 = 0; ch2 < 2; ++ch2) {
                    if (pcol[j][ch2] >= 0) {
                        y_s[(size_t)row * 96 + pcol[j][ch2]] =
                            __float2half_rn(acc[i][j][rh2 * 2 + ch2] +
                                            pbias[j][ch2]);
                    }
                }
            }
        }
    }
    __syncthreads();

    // coalesced global write: g_Ah[(b*NP + v*512 + d0 + m)*88 + (r*8+c)]
    size_t gbase = ((size_t)b * NP + (size_t)v * ND + d0) * OC;
    for (int i = tid; i < MT * (OC / 2); i += NTHR) {
        int od = i / (OC / 2);
        int cu = i - od * (OC / 2);
        ((uint32_t*)(g_Ah + gbase + (size_t)od * OC))[cu] =
            ((const uint32_t*)(y_s + (size_t)od * 96))[cu];
    }
}

// ---------------- gather (round-11 version: hoisted loads, 175.7us) ----------------
__device__ __forceinline__ void stg_cs(float* p, float v) {
    asm volatile("st.global.cs.f32 [%0], %1;" :: "l"(p), "f"(v));
}

__global__ __launch_bounds__(256)
void gather_kernel(const float* __restrict__ idxs, float* __restrict__ out) {
    int j = blockIdx.x * 256 + threadIdx.x;
    if (j >= NIDX) return;

    float t  = idxs[j];
    float il = floorf(t);
    float w  = t - il;
    float w5 = w * 5.0f;
    float fw = floorf(w5);
    float lw = w5 - fw;

    int li = (int)(il * 11.0f + 5.0f + fw);
    int hi = li + 6;
    if (hi >= LL - 1) hi = LL - 2;

    float omlw = 1.0f - lw;
    float omw  = 1.0f - w;

    const __half* T0 = g_Ah;
    const __half* T1 = g_Ah + (size_t)LL * 8u;
    uint4 v0a = __ldg((const uint4*)(T0 + (size_t)li * 8u));
    uint4 v0b = __ldg((const uint4*)(T0 + (size_t)(li + 1) * 8u));
    uint4 u0a = __ldg((const uint4*)(T0 + (size_t)hi * 8u));
    uint4 u0b = __ldg((const uint4*)(T0 + (size_t)(hi + 1) * 8u));
    uint4 v1a = __ldg((const uint4*)(T1 + (size_t)li * 8u));
    uint4 v1b = __ldg((const uint4*)(T1 + (size_t)(li + 1) * 8u));
    uint4 u1a = __ldg((const uint4*)(T1 + (size_t)hi * 8u));
    uint4 u1b = __ldg((const uint4*)(T1 + (size_t)(hi + 1) * 8u));

    const uint4* VA[2] = {&v0a, &v1a};
    const uint4* VB[2] = {&v0b, &v1b};
    const uint4* UA[2] = {&u0a, &u1a};
    const uint4* UB[2] = {&u0b, &u1b};

#pragma unroll
    for (int b = 0; b < 2; ++b) {
        size_t obase = (size_t)b * 8u * (size_t)NIDX + (size_t)j;
#pragma unroll
        for (int p = 0; p < 4; ++p) {
            float2 a0 = __half22float2(((const __half2*)VA[b])[p]);
            float2 a1 = __half22float2(((const __half2*)VB[b])[p]);
            float2 c0 = __half22float2(((const __half2*)UA[b])[p]);
            float2 c1 = __half22float2(((const __half2*)UB[b])[p]);

            float lowx  = a0.x * omlw + a1.x * lw;
            float lowy  = a0.y * omlw + a1.y * lw;
            float highx = c0.x * omlw + c1.x * lw;
            float highy = c0.y * omlw + c1.y * lw;

            stg_cs(out + obase + (size_t)(2 * p + 0) * NIDX, lowx * omw + highx * w);
            stg_cs(out + obase + (size_t)(2 * p + 1) * NIDX, lowy * omw + highy * w);
        }
    }
}

// ---------------- launch ----------------
extern "C" void kernel_launch(void* const* d_in, const int* in_sizes, int n_in,
                              void* d_out, int out_size) {
    const float* input = (const float*)d_in[0];
    const float* idxs  = (const float*)d_in[1];
    const float* fc1w  = (const float*)d_in[2];
    const float* fc1b  = (const float*)d_in[3];
    const float* fc2w  = (const float*)d_in[4];
    const float* fc2b  = (const float*)d_in[5];
    float* out = (float*)d_out;

    cudaFuncSetAttribute(conv_tc, cudaFuncAttributeMaxDynamicSharedMemorySize,
                         SM_TOT);

    knop<<<1, 1>>>();   // alignment: ncu sample (2 hidden + idx 3) -> conv_tc
    prep_B<<<(3 * BIMG + 255) / 256, 256>>>(fc2w);
    knop<<<1, 1>>>();
    conv_tc<<<NB * NV * (ND / MT), NTHR, SM_TOT>>>(input, fc1w, fc1b, fc2b);
    gather_kernel<<<NIDX / 256, 256>>>(idxs, out);
}

// round 14
// speedup vs baseline: 1.3938x; 1.2000x over previous
#include <cuda_runtime.h>
#include <cuda_bf16.h>
#include <cuda_fp16.h>
#include <math.h>
#include <stdint.h>

// ---------------- geometry ----------------
#define NB     2
#define NC     8
#define NV     360
#define ND     512
#define RR     11
#define HID    176
#define OC     88
#define NP     (NV*ND)
#define LL     (NP*RR)
#define NIDX   (128*128*360)

#define MT     128          // d positions per block
#define KPIT   184          // H fp16 col pitch (368B rows -> conflict-free ldmatrix)
#define NTHR   384          // 12 warps

// conv1-as-MMA geometry: M=144 (132 used), N=176, K=32 (24 used)
#define AXP    40           // Axc pitch in halves (80B rows, odd*16 -> conflict-free)
#define B1P    40           // W1 image pitch in halves

// SMEM byte offsets (all 16B aligned)
#define SM_B1s   0          // 176*4  = 704
#define SM_B2s   704        // 96*4   = 384
#define SM_PERM  1088       // 96*4   = 384
#define SM_AX    1472       // 144*80 = 11520
#define SM_B1M   12992      // 176*80 = 14080
#define SM_HB    27072      // 132*368 = 48576
#define SM_BS    75648      // 96*368  = 35328
#define SM_TOT   110976

#define BIMG    (96 * KPIT)             // 17664 halves per tap
#define BCHUNK  (BIMG * 2)              // 35328 bytes
#define B1BYTES (HID * B1P * 2)         // 14080 bytes

// scratch (no cudaMalloc allowed)
__device__ __half g_Ah[2u * (unsigned)LL * 8u];          // fp16 table ~65MB
__device__ __align__(16) __half g_Bimg[3 * BIMG];        // conv2 B taps
__device__ __align__(16) __half g_B1img[HID * B1P];      // conv1 W1 image
__device__ int g_sink;

// ---------------- helpers ----------------
__device__ __forceinline__ uint32_t smem_u32(const void* p) {
    uint32_t a;
    asm("{ .reg .u64 t; cvta.to.shared.u64 t, %1; cvt.u32.u64 %0, t; }"
        : "=r"(a) : "l"(p));
    return a;
}

#define LDM4(d, addr)                                                        \
    asm volatile("ldmatrix.sync.aligned.m8n8.x4.shared.b16 "                 \
                 "{%0,%1,%2,%3}, [%4];"                                      \
                 : "=r"((d)[0]), "=r"((d)[1]), "=r"((d)[2]), "=r"((d)[3])    \
                 : "r"(addr) : "memory")

#define MMA(c, a, b0, b1)                                                    \
    asm volatile("mma.sync.aligned.m16n8k16.row.col.f32.f16.f16.f32 "        \
                 "{%0,%1,%2,%3},{%4,%5,%6,%7},{%8,%9},{%0,%1,%2,%3};"        \
                 : "+f"((c)[0]), "+f"((c)[1]), "+f"((c)[2]), "+f"((c)[3])    \
                 : "r"((a)[0]), "r"((a)[1]), "r"((a)[2]), "r"((a)[3]),       \
                   "r"(b0), "r"(b1))

#define CP16(dst, src)                                                       \
    asm volatile("cp.async.cg.shared.global [%0], [%1], 16;"                 \
                 :: "r"(dst), "l"(src) : "memory")
#define CPCOMMIT() asm volatile("cp.async.commit_group;" ::: "memory")
#define CPWAIT0()  asm volatile("cp.async.wait_group 0;"  ::: "memory")

// tanh-form gelu (~10 instr). |err| ~1.5e-4 abs, below fp16 quant carried.
__device__ __forceinline__ float gelu_f(float x) {
    float t  = x * x;
    float u2 = x * fmaf(0.044715f, t, 1.0f) * 1.5957691216f;  // = 2u
    float e  = __expf(u2);
    float r  = __fdividef(1.0f, e + 1.0f);
    return fmaf(-x, r, x);
}

// ---- dummy: shifts ncu -s alignment so capture lands on conv_tc ----
__global__ void knop() { g_sink = 1; }

// ---- prep: fc2 per-tap fp16 images + fc1 weight image ----
__global__ void prep_B(const float* __restrict__ w2, const float* __restrict__ w1) {
    int i = blockIdx.x * 256 + threadIdx.x;
    if (i < 3 * BIMG) {
        int k = i % KPIT;
        int n = (i / KPIT) % 96;
        int t = i / BIMG;
        float v = 0.f;
        if (n < OC && k < HID) v = w2[((size_t)n * HID + k) * 3 + t];
        g_Bimg[(size_t)t * BIMG + (size_t)n * KPIT + k] = __float2half_rn(v);
    } else {
        int i2 = i - 3 * BIMG;
        if (i2 < HID * B1P) {
            int kp = i2 % B1P;
            int n  = i2 / B1P;
            float v = 0.f;
            if (kp < 24) v = w1[n * 24 + kp];     // w1[hc][ci][t], k=ci*3+t
            g_B1img[i2] = __float2half_rn(v);
        }
    }
}

// ---------------- fully-MMA conv (conv1 GEMM + gelu + conv2 GEMM) ----------------
__global__ __launch_bounds__(NTHR, 2)
void conv_tc(const float* __restrict__ input,
             const float* __restrict__ b1,
             const float* __restrict__ b2) {
    extern __shared__ char smem[];
    const uint32_t sb = smem_u32(smem);
    float* b1s  = (float*)(smem + SM_B1s);
    float* b2s  = (float*)(smem + SM_B2s);
    int*   perm = (int*)(smem + SM_PERM);

    const int tid  = threadIdx.x;
    const int wid  = tid >> 5;
    const int lane = tid & 31;
    const int blk  = blockIdx.x;
    const int tile = blk & 3;
    const int bv   = blk >> 2;
    const int b    = bv / NV;
    const int v    = bv - b * NV;
    const int d0   = tile * MT;

    const int rbase = (lane >> 2);
    const int cbase = (lane & 3) * 2;
    const int g     = lane >> 3;

    // ---- stage biases + perm LUT ----
    for (int i = tid; i < HID; i += NTHR) b1s[i] = b1[i];
    if (tid < OC) {
        b2s[tid] = b2[tid];
        perm[tid] = (tid % RR) * 8 + tid / RR;
    }

    // ---- async prefetch: W1 image + conv2 B tap 0 ----
    {
        const char* s1 = (const char*)g_B1img;
        for (int i = tid; i < B1BYTES / 16; i += NTHR)
            CP16(sb + SM_B1M + i * 16, s1 + i * 16);
        const char* s2 = (const char*)g_Bimg;
        for (int i = tid; i < BCHUNK / 16; i += NTHR)
            CP16(sb + SM_BS + i * 16, s2 + i * 16);
        CPCOMMIT();
    }

    // ---- build Axc im2col fp16 directly from global (coalesced along dd) ----
    __half* axc = (__half*)(smem + SM_AX);
    // zero k-pad columns 24..31
    for (int e = tid; e < 144 * 8; e += NTHR) {
        int dd = e >> 3, kc = 24 + (e & 7);
        axc[dd * AXP + kc] = __float2half_rn(0.f);
    }
    // fill k 0..23: Axc[dd][3ci+t] = x[b,ci,v, d0-2+dd+t]
    for (int e = tid; e < 24 * 144; e += NTHR) {
        int kc = e / 144;
        int dd = e - kc * 144;
        int ci = kc / 3, t = kc - ci * 3;
        int dG = d0 - 2 + dd + t;
        float val = 0.f;
        if ((unsigned)dG < (unsigned)ND)
            val = input[((size_t)(b * NC + ci) * NV + v) * ND + dG];
        axc[dd * AXP + kc] = __float2half_rn(val);
    }
    CPWAIT0();
    __syncthreads();   // Axc + W1 + B tap0 ready

    // ---- conv1 MMA: 11 warps x n16 strips, M=144, K=32 ----
    if (wid < 11) {
        const int n0c = wid * 16;
        uint32_t b1f[2][4];
        const uint32_t bAddr = sb + SM_B1M +
            (uint32_t)(n0c + (g >> 1) * 8 + (lane & 7)) * 80u +
            (uint32_t)(g & 1) * 16u;
        LDM4(b1f[0], bAddr);
        LDM4(b1f[1], bAddr + 32);

        float bj[2][2];
#pragma unroll
        for (int j = 0; j < 2; ++j) {
            int hc0 = n0c + j * 8 + cbase;
            bj[j][0] = b1s[hc0];
            bj[j][1] = b1s[hc0 + 1];
        }

#pragma unroll 1
        for (int mt = 0; mt < 9; ++mt) {
            int m0t = mt * 16;
            uint32_t aAddr = sb + SM_AX +
                (uint32_t)(m0t + (lane & 15)) * 80u +
                (uint32_t)(lane >> 4) * 16u;
            float c1[2][4] = {{0.f,0.f,0.f,0.f},{0.f,0.f,0.f,0.f}};
            uint32_t af[4];
            LDM4(af, aAddr);
            MMA(c1[0], af, b1f[0][0], b1f[0][1]);
            MMA(c1[1], af, b1f[0][2], b1f[0][3]);
            LDM4(af, aAddr + 32);
            MMA(c1[0], af, b1f[1][0], b1f[1][1]);
            MMA(c1[1], af, b1f[1][2], b1f[1][3]);

            // gelu + half2 store into H[dd][hc]
#pragma unroll
            for (int i2 = 0; i2 < 2; ++i2) {
                int dd = m0t + rbase + i2 * 8;
                if (dd < 132) {
                    bool ok = (unsigned)(d0 - 1 + dd) < (unsigned)ND;
#pragma unroll
                    for (int j = 0; j < 2; ++j) {
                        float s0 = 0.f, s1 = 0.f;
                        if (ok) {
                            s0 = gelu_f(c1[j][i2 * 2 + 0] + bj[j][0]);
                            s1 = gelu_f(c1[j][i2 * 2 + 1] + bj[j][1]);
                        }
                        int hc0 = n0c + j * 8 + cbase;
                        *(__half2*)(smem + SM_HB + dd * (KPIT * 2) + hc0 * 2) =
                            __floats2half2_rn(s0, s1);
                    }
                }
            }
        }
    }
    __syncthreads();   // H complete

    // ---- conv2 MMA: 4x3 warp grid, warp tile 32m x 32n, 3 taps ----
    const int m0 = (wid & 3) * 32;
    const int n0 = (wid >> 2) * 32;

    float acc[2][4][4];
#pragma unroll
    for (int i = 0; i < 2; ++i)
#pragma unroll
        for (int j = 0; j < 4; ++j)
#pragma unroll
            for (int q = 0; q < 4; ++q) acc[i][j][q] = 0.f;

    const uint32_t aRel = ((uint32_t)(m0 + (lane & 15)) * KPIT +
                           (uint32_t)(lane >> 4) * 8) * 2;
    const uint32_t bRel = ((uint32_t)(n0 + (g >> 1) * 8 + (lane & 7)) * KPIT +
                           (uint32_t)(g & 1) * 8) * 2;
    const uint32_t ROWB = KPIT * 2;        // 368 bytes

#pragma unroll 1
    for (int t = 0; t < 3; ++t) {
        uint32_t aA = sb + SM_HB + aRel + (uint32_t)t * ROWB;
        uint32_t bB = sb + SM_BS + bRel;

#pragma unroll 1
        for (int ks = 0; ks < 11; ++ks) {
            uint32_t ah0[4], ah1[4];
            LDM4(ah0, aA);
            LDM4(ah1, aA + 16 * ROWB);
            uint32_t bb[2][4];
            LDM4(bb[0], bB);
            LDM4(bb[1], bB + 16 * ROWB);

#pragma unroll
            for (int j = 0; j < 4; ++j) {
                const int jj = j >> 1, pp = (j & 1) * 2;
                MMA(acc[0][j], ah0, bb[jj][pp], bb[jj][pp + 1]);
                MMA(acc[1][j], ah1, bb[jj][pp], bb[jj][pp + 1]);
            }
            aA += 32; bB += 32;
        }

        if (t < 2) {
            __syncthreads();   // B buffer free
            const char* src = (const char*)g_Bimg + (size_t)(t + 1) * BCHUNK;
            for (int i = tid; i < BCHUNK / 16; i += NTHR)
                CP16(sb + SM_BS + i * 16, src + i * 16);
            CPCOMMIT();
            CPWAIT0();
            __syncthreads();
        }
    }

    // ---- epilogue: acc + bias -> fp16, permuted via LUT ----
    int pcol[4][2];
    float pbias[4][2];
#pragma unroll
    for (int j = 0; j < 4; ++j)
#pragma unroll
        for (int ch2 = 0; ch2 < 2; ++ch2) {
            int col = n0 + j * 8 + cbase + ch2;
            if (col < OC) { pcol[j][ch2] = perm[col]; pbias[j][ch2] = b2s[col]; }
            else pcol[j][ch2] = -1;
        }
    __syncthreads();   // all H/perm reads done; reuse region for y staging

    __half* y_s = (__half*)(smem + SM_HB);   // [128][96] halves
#pragma unroll
    for (int i = 0; i < 2; ++i) {
#pragma unroll
        for (int j = 0; j < 4; ++j) {
#pragma unroll
            for (int rh2 = 0; rh2 < 2; ++rh2) {
                int row = m0 + i * 16 + rbase + rh2 * 8;
#pragma unroll
                for (int ch2 = 0; ch2 < 2; ++ch2) {
                    if (pcol[j][ch2] >= 0) {
                        y_s[(size_t)row * 96 + pcol[j][ch2]] =
                            __float2half_rn(acc[i][j][rh2 * 2 + ch2] +
                                            pbias[j][ch2]);
                    }
                }
            }
        }
    }
    __syncthreads();

    // coalesced global write: g_Ah[(b*NP + v*512 + d0 + m)*88 + (r*8+c)]
    size_t gbase = ((size_t)b * NP + (size_t)v * ND + d0) * OC;
    for (int i = tid; i < MT * (OC / 2); i += NTHR) {
        int od = i / (OC / 2);
        int cu = i - od * (OC / 2);
        ((uint32_t*)(g_Ah + gbase + (size_t)od * OC))[cu] =
            ((const uint32_t*)(y_s + (size_t)od * 96))[cu];
    }
}

// ---------------- gather (round-11 version: hoisted loads, 175.7us) ----------------
__device__ __forceinline__ void stg_cs(float* p, float v) {
    asm volatile("st.global.cs.f32 [%0], %1;" :: "l"(p), "f"(v));
}

__global__ __launch_bounds__(256)
void gather_kernel(const float* __restrict__ idxs, float* __restrict__ out) {
    int j = blockIdx.x * 256 + threadIdx.x;
    if (j >= NIDX) return;

    float t  = idxs[j];
    float il = floorf(t);
    float w  = t - il;
    float w5 = w * 5.0f;
    float fw = floorf(w5);
    float lw = w5 - fw;

    int li = (int)(il * 11.0f + 5.0f + fw);
    int hi = li + 6;
    if (hi >= LL - 1) hi = LL - 2;

    float omlw = 1.0f - lw;
    float omw  = 1.0f - w;

    const __half* T0 = g_Ah;
    const __half* T1 = g_Ah + (size_t)LL * 8u;
    uint4 v0a = __ldg((const uint4*)(T0 + (size_t)li * 8u));
    uint4 v0b = __ldg((const uint4*)(T0 + (size_t)(li + 1) * 8u));
    uint4 u0a = __ldg((const uint4*)(T0 + (size_t)hi * 8u));
    uint4 u0b = __ldg((const uint4*)(T0 + (size_t)(hi + 1) * 8u));
    uint4 v1a = __ldg((const uint4*)(T1 + (size_t)li * 8u));
    uint4 v1b = __ldg((const uint4*)(T1 + (size_t)(li + 1) * 8u));
    uint4 u1a = __ldg((const uint4*)(T1 + (size_t)hi * 8u));
    uint4 u1b = __ldg((const uint4*)(T1 + (size_t)(hi + 1) * 8u));

    const uint4* VA[2] = {&v0a, &v1a};
    const uint4* VB[2] = {&v0b, &v1b};
    const uint4* UA[2] = {&u0a, &u1a};
    const uint4* UB[2] = {&u0b, &u1b};

#pragma unroll
    for (int b = 0; b < 2; ++b) {
        size_t obase = (size_t)b * 8u * (size_t)NIDX + (size_t)j;
#pragma unroll
        for (int p = 0; p < 4; ++p) {
            float2 a0 = __half22float2(((const __half2*)VA[b])[p]);
            float2 a1 = __half22float2(((const __half2*)VB[b])[p]);
            float2 c0 = __half22float2(((const __half2*)UA[b])[p]);
            float2 c1 = __half22float2(((const __half2*)UB[b])[p]);

            float lowx  = a0.x * omlw + a1.x * lw;
            float lowy  = a0.y * omlw + a1.y * lw;
            float highx = c0.x * omlw + c1.x * lw;
            float highy = c0.y * omlw + c1.y * lw;

            stg_cs(out + obase + (size_t)(2 * p + 0) * NIDX, lowx * omw + highx * w);
            stg_cs(out + obase + (size_t)(2 * p + 1) * NIDX, lowy * omw + highy * w);
        }
    }
}

// ---------------- launch ----------------
extern "C" void kernel_launch(void* const* d_in, const int* in_sizes, int n_in,
                              void* d_out, int out_size) {
    const float* input = (const float*)d_in[0];
    const float* idxs  = (const float*)d_in[1];
    const float* fc1w  = (const float*)d_in[2];
    const float* fc1b  = (const float*)d_in[3];
    const float* fc2w  = (const float*)d_in[4];
    const float* fc2b  = (const float*)d_in[5];
    float* out = (float*)d_out;

    cudaFuncSetAttribute(conv_tc, cudaFuncAttributeMaxDynamicSharedMemorySize,
                         SM_TOT);

    knop<<<1, 1>>>();   // alignment: ncu sample (2 hidden + idx 3) -> conv_tc
    prep_B<<<(3 * BIMG + HID * B1P + 255) / 256, 256>>>(fc2w, fc1w);
    knop<<<1, 1>>>();
    conv_tc<<<NB * NV * (ND / MT), NTHR, SM_TOT>>>(input, fc1b, fc2b);
    gather_kernel<<<NIDX / 256, 256>>>(idxs, out);
}

// round 15
// speedup vs baseline: 1.5648x; 1.1227x over previous
#include <cuda_runtime.h>
#include <cuda_bf16.h>
#include <cuda_fp16.h>
#include <math.h>
#include <stdint.h>

// ---------------- geometry ----------------
#define NB     2
#define NC     8
#define NV     360
#define ND     512
#define RR     11
#define HID    176
#define OC     88
#define NP     (NV*ND)
#define LL     (NP*RR)
#define NIDX   (128*128*360)

#define MT     128          // d positions per block
#define KPIT   184          // H fp16 col pitch (368B rows -> conflict-free ldmatrix)
#define NTHR   384          // 12 warps

// conv1-as-MMA geometry: M=144 (132 used), N=176, K=32 (24 used)
#define AXP    40
#define B1P    40

// SMEM byte offsets (all 16B aligned)
#define SM_B1s   0          // 176*4  = 704
#define SM_B2s   704        // 96*4   = 384
#define SM_PERM  1088       // 96*4   = 384
#define SM_AX    1472       // 144*80 = 11520
#define SM_B1M   12992      // 176*80 = 14080
#define SM_HB    27072      // 132*368 = 48576
#define SM_BS    75648      // 96*368  = 35328
#define SM_TOT   110976

#define BIMG    (96 * KPIT)             // 17664 halves per tap
#define BCHUNK  (BIMG * 2)              // 35328 bytes
#define B1BYTES (HID * B1P * 2)         // 14080 bytes

// scratch (no cudaMalloc allowed)
// table: [row (=p*11+rr)][b][8ch] fp16 -> 32B entries, 32B aligned, ~65MB
__device__ __align__(32) __half g_Ah2[(size_t)LL * 16];
__device__ __align__(16) __half g_Bimg[3 * BIMG];        // conv2 B taps
__device__ __align__(16) __half g_B1img[HID * B1P];      // conv1 W1 image
__device__ int g_sink;

// ---------------- helpers ----------------
__device__ __forceinline__ uint32_t smem_u32(const void* p) {
    uint32_t a;
    asm("{ .reg .u64 t; cvta.to.shared.u64 t, %1; cvt.u32.u64 %0, t; }"
        : "=r"(a) : "l"(p));
    return a;
}

#define LDM4(d, addr)                                                        \
    asm volatile("ldmatrix.sync.aligned.m8n8.x4.shared.b16 "                 \
                 "{%0,%1,%2,%3}, [%4];"                                      \
                 : "=r"((d)[0]), "=r"((d)[1]), "=r"((d)[2]), "=r"((d)[3])    \
                 : "r"(addr) : "memory")

#define MMA(c, a, b0, b1)                                                    \
    asm volatile("mma.sync.aligned.m16n8k16.row.col.f32.f16.f16.f32 "        \
                 "{%0,%1,%2,%3},{%4,%5,%6,%7},{%8,%9},{%0,%1,%2,%3};"        \
                 : "+f"((c)[0]), "+f"((c)[1]), "+f"((c)[2]), "+f"((c)[3])    \
                 : "r"((a)[0]), "r"((a)[1]), "r"((a)[2]), "r"((a)[3]),       \
                   "r"(b0), "r"(b1))

#define CP16(dst, src)                                                       \
    asm volatile("cp.async.cg.shared.global [%0], [%1], 16;"                 \
                 :: "r"(dst), "l"(src) : "memory")
#define CPCOMMIT() asm volatile("cp.async.commit_group;" ::: "memory")
#define CPWAIT0()  asm volatile("cp.async.wait_group 0;"  ::: "memory")

// tanh-form gelu
__device__ __forceinline__ float gelu_f(float x) {
    float t  = x * x;
    float u2 = x * fmaf(0.044715f, t, 1.0f) * 1.5957691216f;
    float e  = __expf(u2);
    float r  = __fdividef(1.0f, e + 1.0f);
    return fmaf(-x, r, x);
}

// 32B table-entry load with L2 evict_last (v4.b64 form — the one ptxas allows)
__device__ __forceinline__ ulonglong4 ldg_el32(const void* p) {
    ulonglong4 r;
    asm volatile("ld.global.nc.L2::evict_last.v4.b64 {%0,%1,%2,%3}, [%4];"
                 : "=l"(r.x), "=l"(r.y), "=l"(r.z), "=l"(r.w) : "l"(p));
    return r;
}
__device__ __forceinline__ void stg_cs(float* p, float v) {
    asm volatile("st.global.cs.f32 [%0], %1;" :: "l"(p), "f"(v));
}

// ---- dummy: shifts ncu -s alignment so capture lands on gather ----
__global__ void knop() { g_sink = 1; }

// ---- prep: fc2 per-tap fp16 images + fc1 weight image ----
__global__ void prep_B(const float* __restrict__ w2, const float* __restrict__ w1) {
    int i = blockIdx.x * 256 + threadIdx.x;
    if (i < 3 * BIMG) {
        int k = i % KPIT;
        int n = (i / KPIT) % 96;
        int t = i / BIMG;
        float v = 0.f;
        if (n < OC && k < HID) v = w2[((size_t)n * HID + k) * 3 + t];
        g_Bimg[(size_t)t * BIMG + (size_t)n * KPIT + k] = __float2half_rn(v);
    } else {
        int i2 = i - 3 * BIMG;
        if (i2 < HID * B1P) {
            int kp = i2 % B1P;
            int n  = i2 / B1P;
            float v = 0.f;
            if (kp < 24) v = w1[n * 24 + kp];
            g_B1img[i2] = __float2half_rn(v);
        }
    }
}

// ---------------- fully-MMA conv (conv1 GEMM + gelu + conv2 GEMM) ----------------
__global__ __launch_bounds__(NTHR, 2)
void conv_tc(const float* __restrict__ input,
             const float* __restrict__ b1,
             const float* __restrict__ b2) {
    extern __shared__ char smem[];
    const uint32_t sb = smem_u32(smem);
    float* b1s  = (float*)(smem + SM_B1s);
    float* b2s  = (float*)(smem + SM_B2s);
    int*   perm = (int*)(smem + SM_PERM);

    const int tid  = threadIdx.x;
    const int wid  = tid >> 5;
    const int lane = tid & 31;
    const int blk  = blockIdx.x;
    const int tile = blk & 3;
    const int bv   = blk >> 2;
    const int b    = bv / NV;
    const int v    = bv - b * NV;
    const int d0   = tile * MT;

    const int rbase = (lane >> 2);
    const int cbase = (lane & 3) * 2;
    const int g     = lane >> 3;

    // ---- stage biases + perm LUT ----
    for (int i = tid; i < HID; i += NTHR) b1s[i] = b1[i];
    if (tid < OC) {
        b2s[tid] = b2[tid];
        perm[tid] = (tid % RR) * 8 + tid / RR;
    }

    // ---- async prefetch: W1 image + conv2 B tap 0 ----
    {
        const char* s1 = (const char*)g_B1img;
        for (int i = tid; i < B1BYTES / 16; i += NTHR)
            CP16(sb + SM_B1M + i * 16, s1 + i * 16);
        const char* s2 = (const char*)g_Bimg;
        for (int i = tid; i < BCHUNK / 16; i += NTHR)
            CP16(sb + SM_BS + i * 16, s2 + i * 16);
        CPCOMMIT();
    }

    // ---- build Axc im2col fp16 directly from global ----
    __half* axc = (__half*)(smem + SM_AX);
    for (int e = tid; e < 144 * 8; e += NTHR) {
        int dd = e >> 3, kc = 24 + (e & 7);
        axc[dd * AXP + kc] = __float2half_rn(0.f);
    }
    for (int e = tid; e < 24 * 144; e += NTHR) {
        int kc = e / 144;
        int dd = e - kc * 144;
        int ci = kc / 3, t = kc - ci * 3;
        int dG = d0 - 2 + dd + t;
        float val = 0.f;
        if ((unsigned)dG < (unsigned)ND)
            val = input[((size_t)(b * NC + ci) * NV + v) * ND + dG];
        axc[dd * AXP + kc] = __float2half_rn(val);
    }
    CPWAIT0();
    __syncthreads();

    // ---- conv1 MMA: 11 warps x n16 strips, M=144, K=32 ----
    if (wid < 11) {
        const int n0c = wid * 16;
        uint32_t b1f[2][4];
        const uint32_t bAddr = sb + SM_B1M +
            (uint32_t)(n0c + (g >> 1) * 8 + (lane & 7)) * 80u +
            (uint32_t)(g & 1) * 16u;
        LDM4(b1f[0], bAddr);
        LDM4(b1f[1], bAddr + 32);

        float bj[2][2];
#pragma unroll
        for (int j = 0; j < 2; ++j) {
            int hc0 = n0c + j * 8 + cbase;
            bj[j][0] = b1s[hc0];
            bj[j][1] = b1s[hc0 + 1];
        }

#pragma unroll 1
        for (int mt = 0; mt < 9; ++mt) {
            int m0t = mt * 16;
            uint32_t aAddr = sb + SM_AX +
                (uint32_t)(m0t + (lane & 15)) * 80u +
                (uint32_t)(lane >> 4) * 16u;
            float c1[2][4] = {{0.f,0.f,0.f,0.f},{0.f,0.f,0.f,0.f}};
            uint32_t af[4];
            LDM4(af, aAddr);
            MMA(c1[0], af, b1f[0][0], b1f[0][1]);
            MMA(c1[1], af, b1f[0][2], b1f[0][3]);
            LDM4(af, aAddr + 32);
            MMA(c1[0], af, b1f[1][0], b1f[1][1]);
            MMA(c1[1], af, b1f[1][2], b1f[1][3]);

#pragma unroll
            for (int i2 = 0; i2 < 2; ++i2) {
                int dd = m0t + rbase + i2 * 8;
                if (dd < 132) {
                    bool ok = (unsigned)(d0 - 1 + dd) < (unsigned)ND;
#pragma unroll
                    for (int j = 0; j < 2; ++j) {
                        float s0 = 0.f, s1 = 0.f;
                        if (ok) {
                            s0 = gelu_f(c1[j][i2 * 2 + 0] + bj[j][0]);
                            s1 = gelu_f(c1[j][i2 * 2 + 1] + bj[j][1]);
                        }
                        int hc0 = n0c + j * 8 + cbase;
                        *(__half2*)(smem + SM_HB + dd * (KPIT * 2) + hc0 * 2) =
                            __floats2half2_rn(s0, s1);
                    }
                }
            }
        }
    }
    __syncthreads();   // H complete

    // ---- conv2 MMA: 4x3 warp grid, warp tile 32m x 32n, 3 taps ----
    const int m0 = (wid & 3) * 32;
    const int n0 = (wid >> 2) * 32;

    float acc[2][4][4];
#pragma unroll
    for (int i = 0; i < 2; ++i)
#pragma unroll
        for (int j = 0; j < 4; ++j)
#pragma unroll
            for (int q = 0; q < 4; ++q) acc[i][j][q] = 0.f;

    const uint32_t aRel = ((uint32_t)(m0 + (lane & 15)) * KPIT +
                           (uint32_t)(lane >> 4) * 8) * 2;
    const uint32_t bRel = ((uint32_t)(n0 + (g >> 1) * 8 + (lane & 7)) * KPIT +
                           (uint32_t)(g & 1) * 8) * 2;
    const uint32_t ROWB = KPIT * 2;

#pragma unroll 1
    for (int t = 0; t < 3; ++t) {
        uint32_t aA = sb + SM_HB + aRel + (uint32_t)t * ROWB;
        uint32_t bB = sb + SM_BS + bRel;

#pragma unroll 1
        for (int ks = 0; ks < 11; ++ks) {
            uint32_t ah0[4], ah1[4];
            LDM4(ah0, aA);
            LDM4(ah1, aA + 16 * ROWB);
            uint32_t bb[2][4];
            LDM4(bb[0], bB);
            LDM4(bb[1], bB + 16 * ROWB);

#pragma unroll
            for (int j = 0; j < 4; ++j) {
                const int jj = j >> 1, pp = (j & 1) * 2;
                MMA(acc[0][j], ah0, bb[jj][pp], bb[jj][pp + 1]);
                MMA(acc[1][j], ah1, bb[jj][pp], bb[jj][pp + 1]);
            }
            aA += 32; bB += 32;
        }

        if (t < 2) {
            __syncthreads();
            const char* src = (const char*)g_Bimg + (size_t)(t + 1) * BCHUNK;
            for (int i = tid; i < BCHUNK / 16; i += NTHR)
                CP16(sb + SM_BS + i * 16, src + i * 16);
            CPCOMMIT();
            CPWAIT0();
            __syncthreads();
        }
    }

    // ---- epilogue: acc + bias -> fp16, permuted via LUT ----
    int pcol[4][2];
    float pbias[4][2];
#pragma unroll
    for (int j = 0; j < 4; ++j)
#pragma unroll
        for (int ch2 = 0; ch2 < 2; ++ch2) {
            int col = n0 + j * 8 + cbase + ch2;
            if (col < OC) { pcol[j][ch2] = perm[col]; pbias[j][ch2] = b2s[col]; }
            else pcol[j][ch2] = -1;
        }
    __syncthreads();

    __half* y_s = (__half*)(smem + SM_HB);   // [128][96] halves
#pragma unroll
    for (int i = 0; i < 2; ++i) {
#pragma unroll
        for (int j = 0; j < 4; ++j) {
#pragma unroll
            for (int rh2 = 0; rh2 < 2; ++rh2) {
                int row = m0 + i * 16 + rbase + rh2 * 8;
#pragma unroll
                for (int ch2 = 0; ch2 < 2; ++ch2) {
                    if (pcol[j][ch2] >= 0) {
                        y_s[(size_t)row * 96 + pcol[j][ch2]] =
                            __float2half_rn(acc[i][j][rh2 * 2 + ch2] +
                                            pbias[j][ch2]);
                    }
                }
            }
        }
    }
    __syncthreads();

    // ---- global write into interleaved table: entry(row=p*11+rr) = [b0 8ch][b1 8ch]
    // uint32 index = row*8 + b*4 + ci2
    const size_t p0 = (size_t)v * ND + d0;
    uint32_t* dst = (uint32_t*)g_Ah2;
    const int bofs = b * 4;
    for (int i = tid; i < MT * (OC / 2); i += NTHR) {
        int od  = i / (OC / 2);
        int cu  = i - od * (OC / 2);
        int rr  = cu >> 2;
        int ci2 = cu & 3;
        size_t row = (p0 + od) * RR + rr;
        dst[row * 8 + bofs + ci2] = ((const uint32_t*)(y_s + (size_t)od * 96))[cu];
    }
}

// ---------------- gather: 4x 32B batch-interleaved loads ----------------
__global__ __launch_bounds__(256)
void gather_kernel(const float* __restrict__ idxs, float* __restrict__ out) {
    int j = blockIdx.x * 256 + threadIdx.x;
    if (j >= NIDX) return;

    float t  = idxs[j];
    float il = floorf(t);
    float w  = t - il;
    float w5 = w * 5.0f;
    float fw = floorf(w5);
    float lw = w5 - fw;

    int li = (int)(il * 11.0f + 5.0f + fw);
    int hi = li + 6;
    if (hi >= LL - 1) hi = LL - 2;

    float omlw = 1.0f - lw;
    float omw  = 1.0f - w;

    const char* bp = (const char*)g_Ah2;
    ulonglong4 Eli = ldg_el32(bp + (size_t)li * 32u);
    ulonglong4 El1 = ldg_el32(bp + (size_t)(li + 1) * 32u);
    ulonglong4 Ehi = ldg_el32(bp + (size_t)hi * 32u);
    ulonglong4 Eh1 = ldg_el32(bp + (size_t)(hi + 1) * 32u);

    const uint32_t* qli = (const uint32_t*)&Eli;   // [b*4 + p] half2 words
    const uint32_t* ql1 = (const uint32_t*)&El1;
    const uint32_t* qhi = (const uint32_t*)&Ehi;
    const uint32_t* qh1 = (const uint32_t*)&Eh1;

#pragma unroll
    for (int b = 0; b < 2; ++b) {
        size_t obase = (size_t)b * 8u * (size_t)NIDX + (size_t)j;
#pragma unroll
        for (int p = 0; p < 4; ++p) {
            float2 a0 = __half22float2(*(const __half2*)&qli[b * 4 + p]);
            float2 a1 = __half22float2(*(const __half2*)&ql1[b * 4 + p]);
            float2 c0 = __half22float2(*(const __half2*)&qhi[b * 4 + p]);
            float2 c1 = __half22float2(*(const __half2*)&qh1[b * 4 + p]);

            float lowx  = a0.x * omlw + a1.x * lw;
            float lowy  = a0.y * omlw + a1.y * lw;
            float highx = c0.x * omlw + c1.x * lw;
            float highy = c0.y * omlw + c1.y * lw;

            stg_cs(out + obase + (size_t)(2 * p + 0) * NIDX, lowx * omw + highx * w);
            stg_cs(out + obase + (size_t)(2 * p + 1) * NIDX, lowy * omw + highy * w);
        }
    }
}

// ---------------- launch ----------------
extern "C" void kernel_launch(void* const* d_in, const int* in_sizes, int n_in,
                              void* d_out, int out_size) {
    const float* input = (const float*)d_in[0];
    const float* idxs  = (const float*)d_in[1];
    const float* fc1w  = (const float*)d_in[2];
    const float* fc1b  = (const float*)d_in[3];
    const float* fc2w  = (const float*)d_in[4];
    const float* fc2b  = (const float*)d_in[5];
    float* out = (float*)d_out;

    cudaFuncSetAttribute(conv_tc, cudaFuncAttributeMaxDynamicSharedMemorySize,
                         SM_TOT);

    knop<<<1, 1>>>();   // alignment: ncu sample (2 hidden + idx 3) -> gather
    prep_B<<<(3 * BIMG + HID * B1P + 255) / 256, 256>>>(fc2w, fc1w);
    conv_tc<<<NB * NV * (ND / MT), NTHR, SM_TOT>>>(input, fc1b, fc2b);
    gather_kernel<<<NIDX / 256, 256>>>(idxs, out);
}